// round 1
// baseline (speedup 1.0000x reference)
#include <cuda_runtime.h>
#include <math.h>

#define N_NODES 50000
#define N_EDGES 800000
#define NHEAD 8
#define HIDD 32
#define FDIM 256   /* NHEAD*HIDD */
#define NEG_SLOPE 0.2f

// ---------------- scratch (static __device__ allocations) ----------------
__device__ float    g_feat[N_NODES * FDIM];   // projected features of current layer
__device__ float    g_h1  [N_NODES * FDIM];   // layer-1 output (residual input for layer 2)
__device__ float    g_rst [N_NODES * FDIM];   // aggregation accumulator
__device__ float    g_esc [N_EDGES * NHEAD];  // per-edge logits, then per-edge exp(a)
__device__ float    g_el  [N_NODES * NHEAD];
__device__ float    g_er  [N_NODES * NHEAD];
__device__ float    g_den [N_NODES * NHEAD];
__device__ float    g_dnv [N_NODES * NHEAD];
__device__ unsigned g_emx [N_NODES * NHEAD];
__device__ float    g_csum[FDIM];

// order-preserving float<->uint encoding for atomicMax
__device__ __forceinline__ unsigned fenc(float f) {
    unsigned u = __float_as_uint(f);
    return (u & 0x80000000u) ? ~u : (u | 0x80000000u);
}
__device__ __forceinline__ float fdec(unsigned m) {
    return (m & 0x80000000u) ? __uint_as_float(m & 0x7fffffffu)
                             : __uint_as_float(~m);
}

// ---------------- tiled FP32 GEMM: C[M,256] = A[M,K] @ B[K,256] ----------------
#define BM 64
#define BN 64
#define BKK 16
#define TM 4
#define TN 4
__global__ __launch_bounds__(256) void sgemm(const float* __restrict__ A,
                                             const float* __restrict__ B,
                                             float* __restrict__ C,
                                             int M, int K) {
    const int N = FDIM;
    __shared__ float As[BM][BKK];
    __shared__ float Bs[BKK][BN];
    int tid  = threadIdx.x;
    int tcol = tid & 15;
    int trow = tid >> 4;
    int rowBase = blockIdx.y * BM;
    int colBase = blockIdx.x * BN;
    float acc[TM][TN] = {};
    for (int k0 = 0; k0 < K; k0 += BKK) {
#pragma unroll
        for (int i = 0; i < (BM * BKK) / 256; i++) {
            int lin = tid + i * 256;
            int m = lin >> 4, k = lin & 15;
            int gr = rowBase + m;
            As[m][k] = (gr < M) ? A[(long)gr * K + k0 + k] : 0.f;
        }
#pragma unroll
        for (int i = 0; i < (BKK * BN) / 256; i++) {
            int lin = tid + i * 256;
            int kk = lin >> 6, n = lin & 63;
            Bs[kk][n] = B[(long)(k0 + kk) * N + colBase + n];
        }
        __syncthreads();
#pragma unroll
        for (int k = 0; k < BKK; k++) {
            float a[TM], b[TN];
#pragma unroll
            for (int i = 0; i < TM; i++) a[i] = As[trow * TM + i][k];
#pragma unroll
            for (int j = 0; j < TN; j++) b[j] = Bs[k][tcol * TN + j];
#pragma unroll
            for (int i = 0; i < TM; i++)
#pragma unroll
                for (int j = 0; j < TN; j++) acc[i][j] += a[i] * b[j];
        }
        __syncthreads();
    }
#pragma unroll
    for (int i = 0; i < TM; i++) {
        int gr = rowBase + trow * TM + i;
        if (gr < M) {
#pragma unroll
            for (int j = 0; j < TN; j++)
                C[(long)gr * N + colBase + tcol * TN + j] = acc[i][j];
        }
    }
}

// ---------------- node prep: el/er dot-products + reset accumulators ----------------
__global__ __launch_bounds__(256) void node_prep(const float* __restrict__ feat,
                                                 const float* __restrict__ al,
                                                 const float* __restrict__ ar,
                                                 float* __restrict__ el,
                                                 float* __restrict__ er,
                                                 unsigned* __restrict__ emax,
                                                 float* __restrict__ denom,
                                                 float* __restrict__ rst) {
    int warp = (blockIdx.x * blockDim.x + threadIdx.x) >> 5;
    int lane = threadIdx.x & 31;
    if (warp >= N_NODES) return;
    const float* f = feat + (long)warp * FDIM;
    float* r = rst + (long)warp * FDIM;
#pragma unroll
    for (int h = 0; h < NHEAD; h++) {
        float v  = f[h * HIDD + lane];
        float pl = v * al[h * HIDD + lane];
        float pr = v * ar[h * HIDD + lane];
#pragma unroll
        for (int o = 16; o; o >>= 1) {
            pl += __shfl_down_sync(0xffffffffu, pl, o);
            pr += __shfl_down_sync(0xffffffffu, pr, o);
        }
        if (lane == 0) {
            el[warp * NHEAD + h] = pl;
            er[warp * NHEAD + h] = pr;
        }
        r[h * HIDD + lane] = 0.f;
    }
    if (lane < NHEAD) {
        emax [warp * NHEAD + lane] = fenc(-__int_as_float(0x7f800000)); // enc(-inf)
        denom[warp * NHEAD + lane] = 0.f;
    }
}

// ---------------- edge pass 1: logits + segment max ----------------
__global__ __launch_bounds__(256) void edge_max(const int* __restrict__ src,
                                                const int* __restrict__ dst,
                                                const float* __restrict__ el,
                                                const float* __restrict__ er,
                                                float* __restrict__ esc,
                                                unsigned* __restrict__ emax) {
    int e = blockIdx.x * blockDim.x + threadIdx.x;
    if (e >= N_EDGES) return;
    int s = src[e], d = dst[e];
    const float4* el4 = (const float4*)(el + s * NHEAD);
    const float4* er4 = (const float4*)(er + d * NHEAD);
    float4 L0 = el4[0], L1 = el4[1];
    float4 R0 = er4[0], R1 = er4[1];
    float ev[NHEAD];
    ev[0] = L0.x + R0.x; ev[1] = L0.y + R0.y; ev[2] = L0.z + R0.z; ev[3] = L0.w + R0.w;
    ev[4] = L1.x + R1.x; ev[5] = L1.y + R1.y; ev[6] = L1.z + R1.z; ev[7] = L1.w + R1.w;
#pragma unroll
    for (int h = 0; h < NHEAD; h++) {
        float v = ev[h];
        v = (v > 0.f) ? v : NEG_SLOPE * v;
        ev[h] = v;
        atomicMax(&emax[d * NHEAD + h], fenc(v));
    }
    float4* o4 = (float4*)(esc + (long)e * NHEAD);
    o4[0] = make_float4(ev[0], ev[1], ev[2], ev[3]);
    o4[1] = make_float4(ev[4], ev[5], ev[6], ev[7]);
}

// ---------------- edge pass 2: exp + segment sum ----------------
__global__ __launch_bounds__(256) void edge_exp(const int* __restrict__ dst,
                                                float* __restrict__ esc,
                                                const unsigned* __restrict__ emax,
                                                float* __restrict__ denom) {
    int e = blockIdx.x * blockDim.x + threadIdx.x;
    if (e >= N_EDGES) return;
    int d = dst[e];
    float4* e4 = (float4*)(esc + (long)e * NHEAD);
    float4 E0 = e4[0], E1 = e4[1];
    float ev[NHEAD] = {E0.x, E0.y, E0.z, E0.w, E1.x, E1.y, E1.z, E1.w};
#pragma unroll
    for (int h = 0; h < NHEAD; h++) {
        float m = fdec(emax[d * NHEAD + h]);
        float a = expf(ev[h] - m);
        ev[h] = a;
        atomicAdd(&denom[d * NHEAD + h], a);
    }
    e4[0] = make_float4(ev[0], ev[1], ev[2], ev[3]);
    e4[1] = make_float4(ev[4], ev[5], ev[6], ev[7]);
}

// ---------------- denom inverse ----------------
__global__ __launch_bounds__(256) void node_inv(const float* __restrict__ denom,
                                                float* __restrict__ dinv) {
    int i = blockIdx.x * blockDim.x + threadIdx.x;
    if (i >= N_NODES * NHEAD) return;
    float dv = denom[i];
    dinv[i] = (dv == 0.f) ? 1.f : 1.f / dv;
}

// ---------------- edge pass 3 (heavy): alpha-weighted scatter ----------------
__global__ __launch_bounds__(256) void edge_aggr(const int* __restrict__ src,
                                                 const int* __restrict__ dst,
                                                 const float* __restrict__ esc,
                                                 const float* __restrict__ dinv,
                                                 const float* __restrict__ feat,
                                                 float* __restrict__ rst) {
    int e    = (blockIdx.x * blockDim.x + threadIdx.x) >> 5;
    int lane = threadIdx.x & 31;
    if (e >= N_EDGES) return;
    int s = src[e], d = dst[e];
    const float4* a4 = (const float4*)(esc + (long)e * NHEAD);
    const float4* v4 = (const float4*)(dinv + d * NHEAD);
    float4 A0 = a4[0], A1 = a4[1];
    float4 D0 = v4[0], D1 = v4[1];
    float alph[NHEAD];
    alph[0] = A0.x * D0.x; alph[1] = A0.y * D0.y; alph[2] = A0.z * D0.z; alph[3] = A0.w * D0.w;
    alph[4] = A1.x * D1.x; alph[5] = A1.y * D1.y; alph[6] = A1.z * D1.z; alph[7] = A1.w * D1.w;
    const float4* f4 = (const float4*)(feat + (long)s * FDIM);
    float* rbase = rst + (long)d * FDIM;
#pragma unroll
    for (int i = 0; i < 2; i++) {
        int vi = i * 32 + lane;          // float4 index 0..63 within row
        int h  = vi >> 3;                // 8 float4 per head
        float a = alph[h];
        float4 v = f4[vi];
        float* rp = rbase + vi * 4;
        atomicAdd(rp + 0, v.x * a);
        atomicAdd(rp + 1, v.y * a);
        atomicAdd(rp + 2, v.z * a);
        atomicAdd(rp + 3, v.w * a);
    }
}

// ---------------- epilogue: (+residual) + bias -> elu ----------------
__global__ __launch_bounds__(256) void epilogue(const float* __restrict__ rst,
                                                const float* __restrict__ hres,
                                                const float* __restrict__ b,
                                                float* __restrict__ hout) {
    long idx = (long)blockIdx.x * blockDim.x + threadIdx.x; // float4 index
    if (idx >= (long)N_NODES * (FDIM / 4)) return;
    int c4 = (int)(idx & 63);
    float4 v = ((const float4*)rst)[idx];
    if (hres) {
        float4 r = ((const float4*)hres)[idx];
        v.x += r.x; v.y += r.y; v.z += r.z; v.w += r.w;
    }
    float4 bb = ((const float4*)b)[c4];
    v.x += bb.x; v.y += bb.y; v.z += bb.z; v.w += bb.w;
    v.x = (v.x > 0.f) ? v.x : expm1f(v.x);
    v.y = (v.y > 0.f) ? v.y : expm1f(v.y);
    v.z = (v.z > 0.f) ? v.z : expm1f(v.z);
    v.w = (v.w > 0.f) ? v.w : expm1f(v.w);
    ((float4*)hout)[idx] = v;
}

// ---------------- column sum + final GEMV (mean commutes with linear) ----------------
__global__ void zero_csum(float* c) { c[threadIdx.x] = 0.f; }

__global__ __launch_bounds__(256) void colsum_k(const float* __restrict__ h,
                                                float* __restrict__ csum) {
    int col = threadIdx.x;
    int r0  = blockIdx.x * 256;
    int r1  = min(r0 + 256, N_NODES);
    float s = 0.f;
    for (int r = r0; r < r1; r++) s += h[(long)r * FDIM + col];
    atomicAdd(&csum[col], s);
}

__global__ void final_k(const float* __restrict__ csum,
                        const float* __restrict__ Wl,
                        const float* __restrict__ bl,
                        float* __restrict__ out) {
    int j = threadIdx.x; // 0..127
    float s = 0.f;
    for (int c = 0; c < FDIM; c++) s += csum[c] * Wl[c * 128 + j];
    out[j] = s * (1.f / (float)N_NODES) + bl[j];
}

// ---------------- host ----------------
extern "C" void kernel_launch(void* const* d_in, const int* in_sizes, int n_in,
                              void* d_out, int out_size) {
    const float* x   = (const float*)d_in[0];
    const int*   src = (const int*)  d_in[1];
    const int*   dst = (const int*)  d_in[2];
    const float* W1  = (const float*)d_in[3];
    const float* al1 = (const float*)d_in[4];
    const float* ar1 = (const float*)d_in[5];
    const float* b1  = (const float*)d_in[6];
    const float* W2  = (const float*)d_in[7];
    const float* al2 = (const float*)d_in[8];
    const float* ar2 = (const float*)d_in[9];
    const float* b2  = (const float*)d_in[10];
    const float* Wl  = (const float*)d_in[11];
    const float* bl  = (const float*)d_in[12];
    float* out = (float*)d_out;

    float *feat, *h1, *rst, *esc, *el, *er, *den, *dnv, *csum;
    unsigned* emx;
    cudaGetSymbolAddress((void**)&feat, g_feat);
    cudaGetSymbolAddress((void**)&h1,   g_h1);
    cudaGetSymbolAddress((void**)&rst,  g_rst);
    cudaGetSymbolAddress((void**)&esc,  g_esc);
    cudaGetSymbolAddress((void**)&el,   g_el);
    cudaGetSymbolAddress((void**)&er,   g_er);
    cudaGetSymbolAddress((void**)&den,  g_den);
    cudaGetSymbolAddress((void**)&dnv,  g_dnv);
    cudaGetSymbolAddress((void**)&emx,  g_emx);
    cudaGetSymbolAddress((void**)&csum, g_csum);

    dim3 gemm_grid(FDIM / BN, (N_NODES + BM - 1) / BM);
    int nodeWarpBlocks = (N_NODES * 32 + 255) / 256;
    int edgeBlocks     = (N_EDGES + 255) / 256;
    int edgeWarpBlocks = (N_EDGES * 32 + 255) / 256;   // overflows int? 25.6M threads -> fine
    int invBlocks      = (N_NODES * NHEAD + 255) / 256;
    int epiBlocks      = (N_NODES * (FDIM / 4) + 255) / 256;
    int csBlocks       = (N_NODES + 255) / 256;

    // ---- layer 1 (no residual) ----
    sgemm<<<gemm_grid, 256>>>(x, W1, feat, N_NODES, 128);
    node_prep<<<nodeWarpBlocks, 256>>>(feat, al1, ar1, el, er, emx, den, rst);
    edge_max<<<edgeBlocks, 256>>>(src, dst, el, er, esc, emx);
    edge_exp<<<edgeBlocks, 256>>>(dst, esc, emx, den);
    node_inv<<<invBlocks, 256>>>(den, dnv);
    edge_aggr<<<edgeWarpBlocks, 256>>>(src, dst, esc, dnv, feat, rst);
    epilogue<<<epiBlocks, 256>>>(rst, nullptr, b1, h1);

    // ---- layer 2 (identity residual) ----
    sgemm<<<gemm_grid, 256>>>(h1, W2, feat, N_NODES, 256);
    node_prep<<<nodeWarpBlocks, 256>>>(feat, al2, ar2, el, er, emx, den, rst);
    edge_max<<<edgeBlocks, 256>>>(src, dst, el, er, esc, emx);
    edge_exp<<<edgeBlocks, 256>>>(dst, esc, emx, den);
    node_inv<<<invBlocks, 256>>>(den, dnv);
    edge_aggr<<<edgeWarpBlocks, 256>>>(src, dst, esc, dnv, feat, rst);
    epilogue<<<epiBlocks, 256>>>(rst, h1, b2, feat);   // h2 -> feat (feat2 dead)

    // ---- mean_nodes(h2 @ Wl + bl) = (colmean(h2)) @ Wl + bl ----
    zero_csum<<<1, FDIM>>>(csum);
    colsum_k<<<csBlocks, 256>>>(feat, csum);
    final_k<<<1, 128>>>(csum, Wl, bl, out);
}

// round 3
// speedup vs baseline: 2.5013x; 2.5013x over previous
#include <cuda_runtime.h>
#include <math.h>

#define N_NODES 50000
#define N_EDGES 800000
#define NHEAD 8
#define HIDD 32
#define FDIM 256
#define NEG_SLOPE 0.2f

// ---------------- scratch ----------------
__device__ float g_feat[N_NODES * FDIM];
__device__ float g_h1  [N_NODES * FDIM];
__device__ float g_h2  [N_NODES * FDIM];
__device__ float g_el  [N_NODES * NHEAD];
__device__ float g_er  [N_NODES * NHEAD];
__device__ float g_csum[FDIM];
__device__ int   g_cnt [N_NODES];
__device__ int   g_rows[N_NODES + 1];
__device__ int   g_cur [N_NODES];
__device__ int   g_csrc[N_EDGES];

// ================= CSR build =================
__global__ void zero_cnt(int* cnt) {
    int i = blockIdx.x * blockDim.x + threadIdx.x;
    if (i < N_NODES) cnt[i] = 0;
}
__global__ void hist_k(const int* __restrict__ dst, int* __restrict__ cnt) {
    int e = blockIdx.x * blockDim.x + threadIdx.x;
    if (e < N_EDGES) atomicAdd(&cnt[dst[e]], 1);
}
__global__ __launch_bounds__(1024) void scan_k(const int* __restrict__ cnt,
                                               int* __restrict__ rows,
                                               int* __restrict__ cur) {
    __shared__ int warpsum[32];
    __shared__ int s_carry;
    int t = threadIdx.x;
    int lane = t & 31, wid = t >> 5;
    if (t == 0) s_carry = 0;
    __syncthreads();
    for (int base = 0; base < N_NODES; base += 1024) {
        int i = base + t;
        int v = (i < N_NODES) ? cnt[i] : 0;
        int x = v;
#pragma unroll
        for (int o = 1; o < 32; o <<= 1) {
            int y = __shfl_up_sync(0xffffffffu, x, o);
            if (lane >= o) x += y;
        }
        if (lane == 31) warpsum[wid] = x;
        __syncthreads();
        if (wid == 0) {
            int w = warpsum[lane];
#pragma unroll
            for (int o = 1; o < 32; o <<= 1) {
                int y = __shfl_up_sync(0xffffffffu, w, o);
                if (lane >= o) w += y;
            }
            warpsum[lane] = w;
        }
        __syncthreads();
        int incl = x + (wid ? warpsum[wid - 1] : 0);
        int excl = s_carry + incl - v;
        if (i < N_NODES) { rows[i] = excl; cur[i] = excl; }
        __syncthreads();
        if (t == 1023) s_carry += incl;
        __syncthreads();
    }
    if (t == 0) rows[N_NODES] = s_carry;
}
__global__ void scatter_k(const int* __restrict__ src, const int* __restrict__ dst,
                          int* __restrict__ cur, int* __restrict__ csrc) {
    int e = blockIdx.x * blockDim.x + threadIdx.x;
    if (e < N_EDGES) {
        int pos = atomicAdd(&cur[dst[e]], 1);
        csrc[pos] = src[e];
    }
}

// ================= GEMM: C[M,256] = A[M,K] @ B[K,256] =================
#define GM 128
#define GN 128
#define GK 8
__global__ __launch_bounds__(256) void sgemm(const float* __restrict__ A,
                                             const float* __restrict__ B,
                                             float* __restrict__ C,
                                             int M, int K) {
    __shared__ float As[GK][GM];
    __shared__ float Bs[GK][GN];
    int tid = threadIdx.x;
    int trow = tid >> 4, tcol = tid & 15;
    int rowBase = blockIdx.y * GM;
    int colBase = blockIdx.x * GN;

    int ar = tid >> 1;           // 0..127
    int ac = (tid & 1) * 4;      // 0 or 4
    int br = tid >> 5;           // 0..7
    int bc = (tid & 31) * 4;     // 0..124

    float acc[8][8] = {};
    for (int k0 = 0; k0 < K; k0 += GK) {
        // load A tile
        int gr = rowBase + ar;
        float4 av = make_float4(0.f, 0.f, 0.f, 0.f);
        if (gr < M) av = *(const float4*)(A + (long)gr * K + k0 + ac);
        As[ac + 0][ar] = av.x;
        As[ac + 1][ar] = av.y;
        As[ac + 2][ar] = av.z;
        As[ac + 3][ar] = av.w;
        // load B tile
        *(float4*)&Bs[br][bc] = *(const float4*)(B + (long)(k0 + br) * FDIM + colBase + bc);
        __syncthreads();
#pragma unroll
        for (int k = 0; k < GK; k++) {
            float a[8], b[8];
            *(float4*)&a[0] = *(const float4*)&As[k][trow * 8];
            *(float4*)&a[4] = *(const float4*)&As[k][trow * 8 + 4];
            *(float4*)&b[0] = *(const float4*)&Bs[k][tcol * 8];
            *(float4*)&b[4] = *(const float4*)&Bs[k][tcol * 8 + 4];
#pragma unroll
            for (int i = 0; i < 8; i++)
#pragma unroll
                for (int j = 0; j < 8; j++) acc[i][j] += a[i] * b[j];
        }
        __syncthreads();
    }
#pragma unroll
    for (int i = 0; i < 8; i++) {
        int gr = rowBase + trow * 8 + i;
        if (gr < M) {
            float* cp = C + (long)gr * FDIM + colBase + tcol * 8;
            *(float4*)cp       = *(float4*)&acc[i][0];
            *(float4*)(cp + 4) = *(float4*)&acc[i][4];
        }
    }
}

// ================= node prep: el/er =================
__global__ __launch_bounds__(256) void node_prep(const float* __restrict__ feat,
                                                 const float* __restrict__ al,
                                                 const float* __restrict__ ar,
                                                 float* __restrict__ el,
                                                 float* __restrict__ er) {
    int warp = (blockIdx.x * blockDim.x + threadIdx.x) >> 5;
    int lane = threadIdx.x & 31;
    if (warp >= N_NODES) return;
    const float* f = feat + (long)warp * FDIM;
#pragma unroll
    for (int h = 0; h < NHEAD; h++) {
        float v  = f[h * HIDD + lane];
        float pl = v * al[h * HIDD + lane];
        float pr = v * ar[h * HIDD + lane];
#pragma unroll
        for (int o = 16; o; o >>= 1) {
            pl += __shfl_down_sync(0xffffffffu, pl, o);
            pr += __shfl_down_sync(0xffffffffu, pr, o);
        }
        if (lane == 0) {
            el[warp * NHEAD + h] = pl;
            er[warp * NHEAD + h] = pr;
        }
    }
}

// ================= fused per-node GAT aggregation =================
// one warp per dst node. lane owns columns [lane*8, lane*8+8); head = lane>>2.
__global__ __launch_bounds__(256) void gat_aggr(const int* __restrict__ rows,
                                                const int* __restrict__ csrc,
                                                const float* __restrict__ el,
                                                const float* __restrict__ er,
                                                const float* __restrict__ feat,
                                                const float* __restrict__ hres,
                                                const float* __restrict__ bias,
                                                float* __restrict__ hout) {
    int node = (blockIdx.x * blockDim.x + threadIdx.x) >> 5;
    int lane = threadIdx.x & 31;
    if (node >= N_NODES) return;
    int e0 = rows[node], e1 = rows[node + 1];
    int myh = lane >> 2;

    float4 er0 = ((const float4*)(er + node * NHEAD))[0];
    float4 er1 = ((const float4*)(er + node * NHEAD))[1];
    float erh[NHEAD] = {er0.x, er0.y, er0.z, er0.w, er1.x, er1.y, er1.z, er1.w};

    // pass A: per-head max over incoming edges
    float mx[NHEAD];
#pragma unroll
    for (int h = 0; h < NHEAD; h++) mx[h] = -INFINITY;
    for (int e = e0 + lane; e < e1; e += 32) {
        int s = csrc[e];
        float4 l0 = ((const float4*)(el + s * NHEAD))[0];
        float4 l1 = ((const float4*)(el + s * NHEAD))[1];
        float lv[NHEAD] = {l0.x, l0.y, l0.z, l0.w, l1.x, l1.y, l1.z, l1.w};
#pragma unroll
        for (int h = 0; h < NHEAD; h++) {
            float v = lv[h] + erh[h];
            v = (v > 0.f) ? v : NEG_SLOPE * v;
            mx[h] = fmaxf(mx[h], v);
        }
    }
#pragma unroll
    for (int h = 0; h < NHEAD; h++)
#pragma unroll
        for (int o = 16; o; o >>= 1)
            mx[h] = fmaxf(mx[h], __shfl_xor_sync(0xffffffffu, mx[h], o));

    // pass B: exp-weights + denom + weighted feature accumulation, in registers
    float acc[8] = {};
    float den = 0.f;
    float m_my  = mx[myh];
    float er_my = erh[myh];
    const float4* f4 = (const float4*)feat;
    for (int e = e0; e < e1; e++) {
        int s = csrc[e];                      // uniform across warp
        float v = el[s * NHEAD + myh] + er_my;
        v = (v > 0.f) ? v : NEG_SLOPE * v;
        float a = expf(v - m_my);
        den += a;
        float4 v0 = f4[(long)s * 64 + lane * 2];
        float4 v1 = f4[(long)s * 64 + lane * 2 + 1];
        acc[0] += a * v0.x; acc[1] += a * v0.y; acc[2] += a * v0.z; acc[3] += a * v0.w;
        acc[4] += a * v1.x; acc[5] += a * v1.y; acc[6] += a * v1.z; acc[7] += a * v1.w;
    }
    float inv = (den == 0.f) ? 1.f : 1.f / den;

    // epilogue: scale, +residual, +bias, elu
    float4 b0 = ((const float4*)bias)[lane * 2];
    float4 b1 = ((const float4*)bias)[lane * 2 + 1];
    float bv[8] = {b0.x, b0.y, b0.z, b0.w, b1.x, b1.y, b1.z, b1.w};
    float rv[8] = {};
    if (hres) {
        float4 r0 = ((const float4*)(hres + (long)node * FDIM))[lane * 2];
        float4 r1 = ((const float4*)(hres + (long)node * FDIM))[lane * 2 + 1];
        rv[0] = r0.x; rv[1] = r0.y; rv[2] = r0.z; rv[3] = r0.w;
        rv[4] = r1.x; rv[5] = r1.y; rv[6] = r1.z; rv[7] = r1.w;
    }
    float o[8];
#pragma unroll
    for (int j = 0; j < 8; j++) {
        float val = acc[j] * inv + rv[j] + bv[j];
        o[j] = (val > 0.f) ? val : expm1f(val);
    }
    float* op = hout + (long)node * FDIM + lane * 8;
    *(float4*)op       = make_float4(o[0], o[1], o[2], o[3]);
    *(float4*)(op + 4) = make_float4(o[4], o[5], o[6], o[7]);
}

// ================= mean -> linear (commuted) =================
__global__ void zero_csum(float* c) { c[threadIdx.x] = 0.f; }

__global__ __launch_bounds__(256) void colsum_k(const float* __restrict__ h,
                                                float* __restrict__ csum) {
    int col = threadIdx.x;
    int r0 = blockIdx.x * 256;
    int r1 = min(r0 + 256, N_NODES);
    float s = 0.f;
    for (int r = r0; r < r1; r++) s += h[(long)r * FDIM + col];
    atomicAdd(&csum[col], s);
}

__global__ void final_k(const float* __restrict__ csum,
                        const float* __restrict__ Wl,
                        const float* __restrict__ bl,
                        float* __restrict__ out) {
    int j = threadIdx.x;
    float s = 0.f;
    for (int c = 0; c < FDIM; c++) s += csum[c] * Wl[c * 128 + j];
    out[j] = s * (1.f / (float)N_NODES) + bl[j];
}

// ================= host =================
extern "C" void kernel_launch(void* const* d_in, const int* in_sizes, int n_in,
                              void* d_out, int out_size) {
    const float* x   = (const float*)d_in[0];
    const int*   src = (const int*)  d_in[1];
    const int*   dst = (const int*)  d_in[2];
    const float* W1  = (const float*)d_in[3];
    const float* al1 = (const float*)d_in[4];
    const float* ar1 = (const float*)d_in[5];
    const float* b1  = (const float*)d_in[6];
    const float* W2  = (const float*)d_in[7];
    const float* al2 = (const float*)d_in[8];
    const float* ar2 = (const float*)d_in[9];
    const float* b2  = (const float*)d_in[10];
    const float* Wl  = (const float*)d_in[11];
    const float* bl  = (const float*)d_in[12];
    float* out = (float*)d_out;

    float *feat, *h1, *h2, *el, *er, *csum;
    int *cnt, *rows, *cur, *csrc;
    cudaGetSymbolAddress((void**)&feat, g_feat);
    cudaGetSymbolAddress((void**)&h1,   g_h1);
    cudaGetSymbolAddress((void**)&h2,   g_h2);
    cudaGetSymbolAddress((void**)&el,   g_el);
    cudaGetSymbolAddress((void**)&er,   g_er);
    cudaGetSymbolAddress((void**)&csum, g_csum);
    cudaGetSymbolAddress((void**)&cnt,  g_cnt);
    cudaGetSymbolAddress((void**)&rows, g_rows);
    cudaGetSymbolAddress((void**)&cur,  g_cur);
    cudaGetSymbolAddress((void**)&csrc, g_csrc);

    int nodeBlocks     = (N_NODES + 255) / 256;
    int edgeBlocks     = (N_EDGES + 255) / 256;
    int nodeWarpBlocks = (N_NODES * 32 + 255) / 256;
    int csBlocks       = (N_NODES + 255) / 256;
    dim3 gemm_grid(FDIM / GN, (N_NODES + GM - 1) / GM);

    // CSR build (shared by both layers)
    zero_cnt<<<nodeBlocks, 256>>>(cnt);
    hist_k<<<edgeBlocks, 256>>>(dst, cnt);
    scan_k<<<1, 1024>>>(cnt, rows, cur);
    scatter_k<<<edgeBlocks, 256>>>(src, dst, cur, csrc);

    // layer 1 (no residual)
    sgemm<<<gemm_grid, 256>>>(x, W1, feat, N_NODES, 128);
    node_prep<<<nodeWarpBlocks, 256>>>(feat, al1, ar1, el, er);
    gat_aggr<<<nodeWarpBlocks, 256>>>(rows, csrc, el, er, feat, nullptr, b1, h1);

    // layer 2 (identity residual)
    sgemm<<<gemm_grid, 256>>>(h1, W2, feat, N_NODES, 256);
    node_prep<<<nodeWarpBlocks, 256>>>(feat, al2, ar2, el, er);
    gat_aggr<<<nodeWarpBlocks, 256>>>(rows, csrc, el, er, feat, h1, b2, h2);

    // mean_nodes(h2 @ Wl + bl) = colmean(h2) @ Wl + bl
    zero_csum<<<1, FDIM>>>(csum);
    colsum_k<<<csBlocks, 256>>>(h2, csum);
    final_k<<<1, 128>>>(csum, Wl, bl, out);
}